// round 15
// baseline (speedup 1.0000x reference)
#include <cuda_runtime.h>
#include <cstdint>
#include <math.h>

#define DIM   1024
#define HID   2048
#define NE    8
#define TMAX  8192
#define NSLOT (TMAX * 2)

// GEMM tiling: CTA 128x128, 4 warps (2m x 2n), warp tile 64x64, BK=16, 2 CTAs/SM
#define BM 128
#define BN 128
#define BK 16
#define RSB 80                               // row stride bytes (20 floats, LDSM conflict-free)
#define A_STAGE_BYTES (BM * RSB)             // 10240
#define B_STAGE_BYTES (BN * RSB)             // 10240
#define STAGE_BYTES   (A_STAGE_BYTES + B_STAGE_BYTES)
#define SMEM_BYTES    (2 * STAGE_BYTES)      // 40960

// ---------------- static device scratch (~128 MB, proven footprint) ----------------
__device__ int   g_counts[NE];
__device__ int   g_lists[NE * TMAX];
__device__ float g_wslot[NSLOT];
__device__ float g_hbuf[(size_t)NSLOT * HID];   // tf32-pre-rounded hidden acts

// ---------------- helpers ----------------
__device__ __forceinline__ float tf32r(float f) {
    uint32_t u;
    asm("cvt.rna.tf32.f32 %0, %1;" : "=r"(u) : "f"(f));
    return __uint_as_float(u);
}
__device__ __forceinline__ float gelu_exact(float v) {
    return 0.5f * v * (1.0f + erff(v * 0.7071067811865476f));
}
__device__ __forceinline__ uint32_t smem_u32(const void* p) {
    return (uint32_t)__cvta_generic_to_shared(p);
}
__device__ __forceinline__ void mma_tf32(float* c, const uint32_t* a, const uint32_t* b) {
    asm volatile(
        "mma.sync.aligned.m16n8k8.row.col.f32.tf32.tf32.f32 "
        "{%0,%1,%2,%3}, {%4,%5,%6,%7}, {%8,%9}, {%0,%1,%2,%3};"
        : "+f"(c[0]), "+f"(c[1]), "+f"(c[2]), "+f"(c[3])
        : "r"(a[0]), "r"(a[1]), "r"(a[2]), "r"(a[3]), "r"(b[0]), "r"(b[1]));
}
__device__ __forceinline__ void ldsm4(uint32_t* d, uint32_t addr) {
    asm volatile("ldmatrix.sync.aligned.m8n8.x4.shared.b16 {%0,%1,%2,%3}, [%4];"
        : "=r"(d[0]), "=r"(d[1]), "=r"(d[2]), "=r"(d[3]) : "r"(addr));
}
__device__ __forceinline__ void cp16(uint32_t saddr, const void* g) {
    asm volatile("cp.async.cg.shared.global [%0], [%1], 16;" :: "r"(saddr), "l"(g));
}
#define CP_COMMIT asm volatile("cp.async.commit_group;")
#define CP_WAIT0  asm volatile("cp.async.wait_group 0;")

// ---------------- kernel 0: zero routing counters ----------------
__global__ void zero_counts_kernel() {
    if (threadIdx.x < NE) g_counts[threadIdx.x] = 0;
}

// ---------------- gating (uses ORIGINAL x); also zeroes its token's out row ----------------
__global__ void __launch_bounds__(256) gating_kernel(
    const float* __restrict__ x, const float* __restrict__ gw,
    const float* __restrict__ gb, float* __restrict__ logits_out,
    float* __restrict__ out)
{
    const int t = blockIdx.x;
    __shared__ float sx[DIM];
    __shared__ float slog[NE];
    const int tid = threadIdx.x;
    const float* xr = x + (size_t)t * DIM;
    #pragma unroll 2
    for (int i = tid; i < DIM; i += 256) sx[i] = xr[i];
    // zero out row (256 threads x 1 float4 = 1024 floats)
    ((float4*)(out + (size_t)t * DIM))[tid] = make_float4(0.f, 0.f, 0.f, 0.f);
    __syncthreads();

    const int w = tid >> 5, lane = tid & 31;
    const float* gwr = gw + (size_t)w * DIM;
    float s = 0.0f;
    #pragma unroll 8
    for (int i = lane; i < DIM; i += 32) s += sx[i] * gwr[i];
    #pragma unroll
    for (int o = 16; o > 0; o >>= 1) s += __shfl_down_sync(0xffffffffu, s, o);
    if (lane == 0) {
        s += gb[w];
        slog[w] = s;
        if (logits_out) logits_out[(size_t)t * NE + w] = s;
    }
    __syncthreads();

    if (tid == 0) {
        int i0 = 0; float v0 = slog[0];
        #pragma unroll
        for (int i = 1; i < NE; i++) if (slog[i] > v0) { v0 = slog[i]; i0 = i; }
        int i1 = -1; float v1 = -3.4e38f;
        #pragma unroll
        for (int i = 0; i < NE; i++) if (i != i0 && slog[i] > v1) { v1 = slog[i]; i1 = i; }
        float r  = expf(v1 - v0);
        float w0 = 1.0f / (1.0f + r);
        float w1 = r * w0;
        int p0 = atomicAdd(&g_counts[i0], 1);
        g_lists[i0 * TMAX + p0] = t * 2;
        int p1 = atomicAdd(&g_counts[i1], 1);
        g_lists[i1 * TMAX + p1] = t * 2 + 1;
        g_wslot[t * 2]     = w0;
        g_wslot[t * 2 + 1] = w1;
    }
}

// ---------------- compute one BK=16 chunk ----------------
__device__ __forceinline__ void compute_chunk(
    uint32_t aA, uint32_t bA, float acc[4][8][4])
{
    #pragma unroll
    for (int ks = 0; ks < 2; ks++) {
        uint32_t a[4][4];
        #pragma unroll
        for (int mt = 0; mt < 4; mt++)
            ldsm4(a[mt], aA + mt * 16 * RSB + ks * 32);
        #pragma unroll
        for (int ntp = 0; ntp < 4; ntp++) {
            uint32_t b[4];
            ldsm4(b, bA + ntp * 16 * RSB + ks * 32);
            #pragma unroll
            for (int mt = 0; mt < 4; mt++) {
                mma_tf32(acc[mt][2 * ntp],     a[mt], b);
                mma_tf32(acc[mt][2 * ntp + 1], a[mt], b + 2);
            }
        }
    }
}

// ---------------- GEMM1: h = round(gelu(x_e @ W1 + b1)) -> g_hbuf ----------------
// A: LDG + cvt.rna + STS (x must be rounded). B: strided LDG + cvt.rna + STS.
__global__ void __launch_bounds__(128, 2) gemm1_kernel(
    const float* __restrict__ x, const float* __restrict__ W1,
    const float* __restrict__ b1)
{
    const int e   = blockIdx.z;
    const int cnt = g_counts[e];
    const int m0  = blockIdx.y * BM;
    if (m0 >= cnt) return;
    const int n0  = blockIdx.x * BN;

    extern __shared__ char smem[];
    __shared__ int sSlot[BM];

    const int tid = threadIdx.x, wid = tid >> 5, lane = tid & 31;
    {
        int gr = m0 + tid;
        sSlot[tid] = (gr < cnt) ? g_lists[e * TMAX + gr] : -1;
    }
    __syncthreads();

    const int aslot = sSlot[tid];
    const float* aPtr = x + (size_t)(aslot >= 0 ? (aslot >> 1) : 0) * DIM;
    const float* bPtr = W1 + (size_t)e * DIM * HID + n0 + tid;

    const int a_row = ((lane >> 3) & 1) * 8 + (lane & 7);
    const int a_k   = ((lane >> 4) & 1) * 4;
    const int b_n   = (lane & 7) + ((lane >> 4) & 1) * 8;
    const int b_k   = ((lane >> 3) & 1) * 4;
    const int warp_m = wid & 1, warp_n = wid >> 1;
    const int g = lane >> 2, t4 = lane & 3;
    const uint32_t sbase = smem_u32(smem);
    const uint32_t aAddr = sbase + (uint32_t)(warp_m * 64 + a_row) * RSB + a_k * 4;
    const uint32_t bAddr = sbase + A_STAGE_BYTES + (uint32_t)(warp_n * 64 + b_n) * RSB + b_k * 4;
    const uint32_t fillOff = (uint32_t)tid * RSB;

    float4 ra[4];
    float  rb[16];
    auto ldg = [&](int kt) {
        const float4* ap = (const float4*)(aPtr + kt * BK);
        #pragma unroll
        for (int i = 0; i < 4; i++) ra[i] = ap[i];
        const float* bp = bPtr + (size_t)kt * BK * HID;
        #pragma unroll
        for (int j = 0; j < 16; j++) rb[j] = bp[(size_t)j * HID];
    };
    auto sts = [&](int stage) {
        char* as = smem + stage * STAGE_BYTES + fillOff;
        #pragma unroll
        for (int i = 0; i < 4; i++) {
            float4 v = ra[i];
            v.x = tf32r(v.x); v.y = tf32r(v.y); v.z = tf32r(v.z); v.w = tf32r(v.w);
            *(float4*)(as + 16 * i) = v;
        }
        char* bs = smem + stage * STAGE_BYTES + A_STAGE_BYTES + fillOff;
        #pragma unroll
        for (int q = 0; q < 4; q++) {
            float4 w;
            w.x = tf32r(rb[4 * q + 0]); w.y = tf32r(rb[4 * q + 1]);
            w.z = tf32r(rb[4 * q + 2]); w.w = tf32r(rb[4 * q + 3]);
            *(float4*)(bs + 16 * q) = w;
        }
    };

    float acc[4][8][4];
    #pragma unroll
    for (int mt = 0; mt < 4; mt++)
        #pragma unroll
        for (int nt = 0; nt < 8; nt++)
            #pragma unroll
            for (int i = 0; i < 4; i++) acc[mt][nt][i] = 0.0f;

    const int KT = DIM / BK;   // 64
    ldg(0); sts(0);
    ldg(1);
    __syncthreads();

    for (int kt = 0; kt < KT; kt++) {
        if (kt + 1 < KT) sts((kt + 1) & 1);
        if (kt + 2 < KT) ldg(kt + 2);
        const uint32_t st = (uint32_t)(kt & 1) * STAGE_BYTES;
        compute_chunk(aAddr + st, bAddr + st, acc);
        __syncthreads();
    }

    // epilogue: bias + exact GELU, tf32-round, scatter rows to g_hbuf[slot]
    const float* b1g = b1 + (size_t)e * HID + n0;
    #pragma unroll
    for (int mt = 0; mt < 4; mt++) {
        const int r0 = warp_m * 64 + mt * 16 + g;
        const int r1 = r0 + 8;
        const bool v0 = (m0 + r0) < cnt;
        const bool v1 = (m0 + r1) < cnt;
        float* h0 = v0 ? (g_hbuf + (size_t)sSlot[r0] * HID + n0) : (float*)0;
        float* h1 = v1 ? (g_hbuf + (size_t)sSlot[r1] * HID + n0) : (float*)0;
        #pragma unroll
        for (int nt = 0; nt < 8; nt++) {
            const int col = warp_n * 64 + nt * 8 + 2 * t4;
            const float bb0 = b1g[col], bb1 = b1g[col + 1];
            if (v0) {
                float2 hv;
                hv.x = tf32r(gelu_exact(acc[mt][nt][0] + bb0));
                hv.y = tf32r(gelu_exact(acc[mt][nt][1] + bb1));
                *(float2*)(h0 + col) = hv;
            }
            if (v1) {
                float2 hv;
                hv.x = tf32r(gelu_exact(acc[mt][nt][2] + bb0));
                hv.y = tf32r(gelu_exact(acc[mt][nt][3] + bb1));
                *(float2*)(h1 + col) = hv;
            }
        }
    }
}

// ---------------- GEMM2: out[token] += w * (h_e @ W2 + b2) ----------------
// A (pre-rounded g_hbuf, contiguous) via cp.async single-pass; B via LDG+cvt+STS.
__global__ void __launch_bounds__(128, 2) gemm2_kernel(
    const float* __restrict__ W2, const float* __restrict__ b2,
    float* __restrict__ out)
{
    const int e   = blockIdx.z;
    const int cnt = g_counts[e];
    const int m0  = blockIdx.y * BM;
    if (m0 >= cnt) return;
    const int n0  = blockIdx.x * BN;

    extern __shared__ char smem[];
    __shared__ int sSlot[BM];

    const int tid = threadIdx.x, wid = tid >> 5, lane = tid & 31;
    {
        int gr = m0 + tid;
        sSlot[tid] = (gr < cnt) ? g_lists[e * TMAX + gr] : -1;
    }
    __syncthreads();

    const int aslot = sSlot[tid];
    const float* aPtr = g_hbuf + (size_t)(aslot >= 0 ? aslot : 0) * HID;
    const float* bPtr = W2 + (size_t)e * HID * DIM + n0 + tid;

    const int a_row = ((lane >> 3) & 1) * 8 + (lane & 7);
    const int a_k   = ((lane >> 4) & 1) * 4;
    const int b_n   = (lane & 7) + ((lane >> 4) & 1) * 8;
    const int b_k   = ((lane >> 3) & 1) * 4;
    const int warp_m = wid & 1, warp_n = wid >> 1;
    const int g = lane >> 2, t4 = lane & 3;
    const uint32_t sbase = smem_u32(smem);
    const uint32_t aAddr = sbase + (uint32_t)(warp_m * 64 + a_row) * RSB + a_k * 4;
    const uint32_t bAddr = sbase + A_STAGE_BYTES + (uint32_t)(warp_n * 64 + b_n) * RSB + b_k * 4;
    const uint32_t fillOff = (uint32_t)tid * RSB;

    float rb[16];
    auto cpA = [&](int kt, int stage) {
        const uint32_t as = sbase + stage * STAGE_BYTES + fillOff;
        const float* ap = aPtr + kt * BK;
        #pragma unroll
        for (int i = 0; i < 4; i++) cp16(as + 16 * i, ap + 4 * i);
        CP_COMMIT;
    };
    auto ldgB = [&](int kt) {
        const float* bp = bPtr + (size_t)kt * BK * DIM;
        #pragma unroll
        for (int j = 0; j < 16; j++) rb[j] = bp[(size_t)j * DIM];
    };
    auto stsB = [&](int stage) {
        char* bs = smem + stage * STAGE_BYTES + A_STAGE_BYTES + fillOff;
        #pragma unroll
        for (int q = 0; q < 4; q++) {
            float4 w;
            w.x = tf32r(rb[4 * q + 0]); w.y = tf32r(rb[4 * q + 1]);
            w.z = tf32r(rb[4 * q + 2]); w.w = tf32r(rb[4 * q + 3]);
            *(float4*)(bs + 16 * q) = w;
        }
    };

    float acc[4][8][4];
    #pragma unroll
    for (int mt = 0; mt < 4; mt++)
        #pragma unroll
        for (int nt = 0; nt < 8; nt++)
            #pragma unroll
            for (int i = 0; i < 4; i++) acc[mt][nt][i] = 0.0f;

    const int KT = HID / BK;   // 128
    cpA(0, 0);
    ldgB(0); stsB(0);
    ldgB(1);
    CP_WAIT0;
    __syncthreads();

    for (int kt = 0; kt < KT; kt++) {
        // issue next stage A early (cp.async latency covered by this chunk's compute)
        if (kt + 1 < KT) { cpA(kt + 1, (kt + 1) & 1); stsB((kt + 1) & 1); }
        if (kt + 2 < KT) ldgB(kt + 2);
        const uint32_t st = (uint32_t)(kt & 1) * STAGE_BYTES;
        compute_chunk(aAddr + st, bAddr + st, acc);
        if (kt + 1 < KT) CP_WAIT0;
        __syncthreads();
    }

    // epilogue: v = w * (acc + bias), atomic scatter to out[token]
    const float* b2g = b2 + (size_t)e * DIM + n0;
    #pragma unroll
    for (int mt = 0; mt < 4; mt++) {
        const int r0 = warp_m * 64 + mt * 16 + g;
        const int r1 = r0 + 8;
        const bool v0 = (m0 + r0) < cnt;
        const bool v1 = (m0 + r1) < cnt;
        int   s0 = v0 ? sSlot[r0] : 0;
        int   s1 = v1 ? sSlot[r1] : 0;
        float w0 = v0 ? g_wslot[s0] : 0.0f;
        float w1 = v1 ? g_wslot[s1] : 0.0f;
        float* o0 = out + (size_t)(s0 >> 1) * DIM + n0;
        float* o1 = out + (size_t)(s1 >> 1) * DIM + n0;
        #pragma unroll
        for (int nt = 0; nt < 8; nt++) {
            const int col = warp_n * 64 + nt * 8 + 2 * t4;
            const float bb0 = b2g[col], bb1 = b2g[col + 1];
            if (v0) {
                atomicAdd(o0 + col,     w0 * (acc[mt][nt][0] + bb0));
                atomicAdd(o0 + col + 1, w0 * (acc[mt][nt][1] + bb1));
            }
            if (v1) {
                atomicAdd(o1 + col,     w1 * (acc[mt][nt][2] + bb0));
                atomicAdd(o1 + col + 1, w1 * (acc[mt][nt][3] + bb1));
            }
        }
    }
}

// ---------------- launch ----------------
extern "C" void kernel_launch(void* const* d_in, const int* in_sizes, int n_in,
                              void* d_out, int out_size)
{
    const float* x  = (const float*)d_in[0];
    const float* gw = (const float*)d_in[1];
    const float* gb = (const float*)d_in[2];
    const float* W1 = (const float*)d_in[3];
    const float* b1 = (const float*)d_in[4];
    const float* W2 = (const float*)d_in[5];
    const float* b2 = (const float*)d_in[6];
    float* out = (float*)d_out;

    const int T = in_sizes[0] / DIM;  // 8192
    float* logits = 0;
    if (out_size >= T * DIM + T * NE) logits = out + (size_t)T * DIM;

    cudaFuncSetAttribute(gemm1_kernel, cudaFuncAttributeMaxDynamicSharedMemorySize, SMEM_BYTES);
    cudaFuncSetAttribute(gemm2_kernel, cudaFuncAttributeMaxDynamicSharedMemorySize, SMEM_BYTES);

    zero_counts_kernel<<<1, 32>>>();
    gating_kernel<<<T, 256>>>(x, gw, gb, logits, out);   // also zeroes out rows

    const int mt = T / BM;  // worst-case M tiles per expert (64)
    gemm1_kernel<<<dim3(HID / BN, mt, NE), 128, SMEM_BYTES>>>(x, W1, b1);
    gemm2_kernel<<<dim3(DIM / BN, mt, NE), 128, SMEM_BYTES>>>(W2, b2, out);
}